// round 2
// baseline (speedup 1.0000x reference)
#include <cuda_runtime.h>
#include <math.h>

#define FULLMASK 0xffffffffu

#define BB   2
#define NN   2048
#define HH   8
#define HID  128
#define VD   16
#define BN   (BB * NN)
// locality=5 -> pos=0.05*2047=102.35 -> need 103rd smallest (0-indexed 102)
#define KTH  103

#define GEMM_SMEM ((HID * HID + 32 * HID) * 4)  /* 81920 B */
#define VTILE 512
#define VSTRIDE 18
#define ATTN_SMEM (VTILE * VSTRIDE * 4)         /* 36864 B */

// ---------------- scratch (device globals; no allocation) ----------------
__device__ float  g_en[BN * HID];
__device__ float  g_x [BN * HID];
__device__ float  g_h [BN * HID];
__device__ float  g_t [BN * HID];
__device__ float  g_r [BN * HID];
__device__ float  g_v [BN * HID];
__device__ float  g_wcat[HID * HID];
__device__ float2 g_rowstats[BN];

__device__ __forceinline__ float gelu_f(float x) {
    // exact (erf) gelu, matching jax.nn.gelu(approximate=False)
    return 0.5f * x * (1.0f + erff(x * 0.70710678118654752f));
}

// ---------------- per-row order statistics of m_dist ----------------
// For each of the B*N rows (length N): min and the 103rd-smallest value.
// Monotonicity of m -> m*r^2 makes these sufficient for the softmax max and
// the percentile mask of both masked mhpas, for all heads. Exact selection
// via binary search on the nonnegative-float bit pattern (values in [0,1)).
__global__ void rowstats_kernel(const float* __restrict__ md, float2* __restrict__ rs) {
    int warp = threadIdx.x >> 5, lane = threadIdx.x & 31;
    int row = blockIdx.x * 8 + warp;
    const float* p = md + (size_t)row * NN + lane;
    unsigned mu[64];
    float mn = 1e30f;
#pragma unroll
    for (int i = 0; i < 64; ++i) {
        float x = p[i * 32];
        mn = fminf(mn, x);
        mu[i] = __float_as_uint(x);
    }
#pragma unroll
    for (int off = 16; off; off >>= 1)
        mn = fminf(mn, __shfl_xor_sync(FULLMASK, mn, off));

    unsigned lo = 0u, hi = 0x3F800000u;  // bit patterns of [0,1)
    while (hi - lo > 1u) {
        unsigned mid = (lo + hi) >> 1;
        int c = 0;
#pragma unroll
        for (int i = 0; i < 64; ++i) c += (mu[i] <= mid) ? 1 : 0;
        c = __reduce_add_sync(FULLMASK, c);
        if (c >= KTH) hi = mid; else lo = mid;
    }
    if (lane == 0) rs[row] = make_float2(mn, __uint_as_float(hi));
}

// ---------------- encoder: gelu(inputs @ en_W + en_b), K=3 ----------------
__global__ void enc_kernel(const float* __restrict__ inp, const float* __restrict__ W,
                           const float* __restrict__ bvec, float* __restrict__ out) {
    int token = blockIdx.x, c = threadIdx.x;
    float x0 = inp[token * 3 + 0];
    float x1 = inp[token * 3 + 1];
    float x2 = inp[token * 3 + 2];
    float s = bvec[c];
    s = fmaf(x0, W[c], s);
    s = fmaf(x1, W[HID + c], s);
    s = fmaf(x2, W[2 * HID + c], s);
    out[(size_t)token * HID + c] = gelu_f(s);
}

// ---------------- repack head weights (H,HID,VD) -> (HID, H*VD) ----------------
__global__ void repack_kernel(const float* __restrict__ w, float* __restrict__ wc) {
    int idx = blockIdx.x * 256 + threadIdx.x;  // 16384 total
    int k = idx >> 7, c = idx & 127;
    wc[idx] = w[(c >> 4) * (HID * VD) + k * VD + (c & 15)];
}

// ---------------- generic 4096x128 @ 128x128 GEMM ----------------
// out[m,c] = act( A[m,:]@W[:,c] + bias[c] (+ res[m,c]) ), act: 0=none, 1=gelu
__global__ void __launch_bounds__(256) gemm128_kernel(
    const float* __restrict__ A, const float* __restrict__ W,
    const float* __restrict__ bias, const float* __restrict__ res,
    float* __restrict__ out, int act)
{
    extern __shared__ float sm[];
    float* Ws = sm;             // 128x128
    float* As = sm + HID * HID; // 32x128
    int tid = threadIdx.x;

    const float4* W4 = (const float4*)W;
    float4* Ws4 = (float4*)Ws;
#pragma unroll
    for (int i = tid; i < HID * HID / 4; i += 256) Ws4[i] = W4[i];

    int row0 = blockIdx.x * 32;
    const float4* A4 = (const float4*)(A + (size_t)row0 * HID);
    float4* As4 = (float4*)As;
#pragma unroll
    for (int i = tid; i < 32 * HID / 4; i += 256) As4[i] = A4[i];
    __syncthreads();

    int cg = tid & 31, rg = tid >> 5;
    int c0 = cg * 4, r0 = rg * 4;
    float acc[4][4];
#pragma unroll
    for (int i = 0; i < 4; ++i)
#pragma unroll
        for (int j = 0; j < 4; ++j) acc[i][j] = 0.f;

#pragma unroll 4
    for (int k = 0; k < HID; ++k) {
        float4 wv = *(const float4*)(Ws + k * HID + c0);
        float a0 = As[(r0 + 0) * HID + k];
        float a1 = As[(r0 + 1) * HID + k];
        float a2 = As[(r0 + 2) * HID + k];
        float a3 = As[(r0 + 3) * HID + k];
        acc[0][0] = fmaf(a0, wv.x, acc[0][0]); acc[0][1] = fmaf(a0, wv.y, acc[0][1]);
        acc[0][2] = fmaf(a0, wv.z, acc[0][2]); acc[0][3] = fmaf(a0, wv.w, acc[0][3]);
        acc[1][0] = fmaf(a1, wv.x, acc[1][0]); acc[1][1] = fmaf(a1, wv.y, acc[1][1]);
        acc[1][2] = fmaf(a1, wv.z, acc[1][2]); acc[1][3] = fmaf(a1, wv.w, acc[1][3]);
        acc[2][0] = fmaf(a2, wv.x, acc[2][0]); acc[2][1] = fmaf(a2, wv.y, acc[2][1]);
        acc[2][2] = fmaf(a2, wv.z, acc[2][2]); acc[2][3] = fmaf(a2, wv.w, acc[2][3]);
        acc[3][0] = fmaf(a3, wv.x, acc[3][0]); acc[3][1] = fmaf(a3, wv.y, acc[3][1]);
        acc[3][2] = fmaf(a3, wv.z, acc[3][2]); acc[3][3] = fmaf(a3, wv.w, acc[3][3]);
    }

    float4 bv = make_float4(0.f, 0.f, 0.f, 0.f);
    if (bias) bv = *(const float4*)(bias + c0);
#pragma unroll
    for (int i = 0; i < 4; ++i) {
        int row = row0 + r0 + i;
        float o0 = acc[i][0] + bv.x;
        float o1 = acc[i][1] + bv.y;
        float o2 = acc[i][2] + bv.z;
        float o3 = acc[i][3] + bv.w;
        if (res) {
            float4 rv = *(const float4*)(res + (size_t)row * HID + c0);
            o0 += rv.x; o1 += rv.y; o2 += rv.z; o3 += rv.w;
        }
        if (act) { o0 = gelu_f(o0); o1 = gelu_f(o1); o2 = gelu_f(o2); o3 = gelu_f(o3); }
        *(float4*)(out + (size_t)row * HID + c0) = make_float4(o0, o1, o2, o3);
    }
}

// ---------------- fused percentile-softmax attention + gelu ----------------
// One CTA per (64 rows, head h, batch b). v_h (2048x16 fp32) staged in smem in
// 4 tiles of 512 rows (stride 18: conflict-free for the LDS.64 pattern).
// Warp handles 8 rows; lane = (jl 0..15 j-slot, dh 0..1 dim half); each lane
// accumulates acc[8 rows][8 dims]. w = exp(min_sd - sd); masked entries 0.
template <int MASKED>
__global__ void __launch_bounds__(256) attn_kernel(
    const float* __restrict__ md, const float* __restrict__ v,
    const float* __restrict__ rvec, const float2* __restrict__ rs,
    float* __restrict__ out)
{
    extern __shared__ float vs[];
    int b = blockIdx.z, h = blockIdx.y;
    float rr = rvec[h];
    float r2 = rr * rr;

    int lane = threadIdx.x & 31, warp = threadIdx.x >> 5;
    int jl = lane & 15, dh = lane >> 4;
    int n0 = blockIdx.x * 64 + warp * 8;

    const float* vg = v + (size_t)b * NN * HID + h * VD;

    float msd[8], s102[8], wsum[8], acc[8][8];
#pragma unroll
    for (int g = 0; g < 8; ++g) {
        float2 st = rs[b * NN + n0 + g];
        msd[g]  = st.x * r2;   // == min_j(sd) exactly (fp mult by r2>0 is monotone)
        s102[g] = st.y;
        wsum[g] = 0.f;
#pragma unroll
        for (int d = 0; d < 8; ++d) acc[g][d] = 0.f;
    }

    const float* mrow = md + ((size_t)b * NN + n0) * NN + jl;

    for (int tt = 0; tt < NN / VTILE; ++tt) {
        __syncthreads();
        // stage v tile (float2, stride-18 rows)
        for (int idx = threadIdx.x; idx < VTILE * 8; idx += 256) {
            int jj = idx >> 3, d2 = (idx & 7) << 1;
            float2 val = *(const float2*)(vg + (size_t)(tt * VTILE + jj) * HID + d2);
            *(float2*)(vs + jj * VSTRIDE + d2) = val;
        }
        __syncthreads();

#pragma unroll 2
        for (int t = 0; t < VTILE / 16; ++t) {
            int jbase = tt * VTILE + t * 16;
            const float* vrow = vs + (t * 16 + jl) * VSTRIDE + dh * 8;
            float2 v0 = *(const float2*)(vrow + 0);
            float2 v1 = *(const float2*)(vrow + 2);
            float2 v2 = *(const float2*)(vrow + 4);
            float2 v3 = *(const float2*)(vrow + 6);
#pragma unroll
            for (int g = 0; g < 8; ++g) {
                float m = mrow[(size_t)g * NN + jbase];
                float e = __expf(fmaf(-m, r2, msd[g]));
                float w = MASKED ? ((m <= s102[g]) ? e : 0.f) : e;
                wsum[g] += w;
                acc[g][0] = fmaf(w, v0.x, acc[g][0]);
                acc[g][1] = fmaf(w, v0.y, acc[g][1]);
                acc[g][2] = fmaf(w, v1.x, acc[g][2]);
                acc[g][3] = fmaf(w, v1.y, acc[g][3]);
                acc[g][4] = fmaf(w, v2.x, acc[g][4]);
                acc[g][5] = fmaf(w, v2.y, acc[g][5]);
                acc[g][6] = fmaf(w, v3.x, acc[g][6]);
                acc[g][7] = fmaf(w, v3.y, acc[g][7]);
            }
        }
    }

    // reduce over the 16 jl slots (stays within each dh half: xor bits 0..3)
#pragma unroll
    for (int off = 8; off; off >>= 1) {
#pragma unroll
        for (int g = 0; g < 8; ++g) {
            wsum[g] += __shfl_xor_sync(FULLMASK, wsum[g], off);
#pragma unroll
            for (int d = 0; d < 8; ++d)
                acc[g][d] += __shfl_xor_sync(FULLMASK, acc[g][d], off);
        }
    }

    if (jl < 8) {
        int g = jl;
        float inv = 1.0f / wsum[g];
        float o[8];
#pragma unroll
        for (int d = 0; d < 8; ++d) o[d] = gelu_f(acc[g][d] * inv);
        float* dst = out + ((size_t)(b * NN + n0 + g)) * HID + h * VD + dh * 8;
        *(float4*)(dst + 0) = make_float4(o[0], o[1], o[2], o[3]);
        *(float4*)(dst + 4) = make_float4(o[4], o[5], o[6], o[7]);
    }
}

// ---------------- final 128 -> 1 projection ----------------
__global__ void final_kernel(const float* __restrict__ t, const float* __restrict__ W,
                             const float* __restrict__ bvec, float* __restrict__ out) {
    int warp = threadIdx.x >> 5, lane = threadIdx.x & 31;
    int token = blockIdx.x * 8 + warp;
    const float* p = t + (size_t)token * HID;
    float s = 0.f;
#pragma unroll
    for (int i = 0; i < 4; ++i) s = fmaf(p[lane + 32 * i], W[lane + 32 * i], s);
#pragma unroll
    for (int off = 16; off; off >>= 1) s += __shfl_xor_sync(FULLMASK, s, off);
    if (lane == 0) out[token] = s + bvec[0];
}

// ---------------- orchestration ----------------
static float* symf(const void* sym) {
    void* p = nullptr;
    cudaGetSymbolAddress(&p, sym);
    return (float*)p;
}

extern "C" void kernel_launch(void* const* d_in, const int* in_sizes, int n_in,
                              void* d_out, int out_size) {
    const float* md      = (const float*)d_in[0];
    const float* inputs  = (const float*)d_in[1];
    const float* en_W    = (const float*)d_in[2];
    const float* en_b    = (const float*)d_in[3];
    const float* down_r  = (const float*)d_in[4];
    const float* down_w  = (const float*)d_in[5];
    const float* mlp1_W1 = (const float*)d_in[6];
    const float* mlp1_b1 = (const float*)d_in[7];
    const float* mlp1_W2 = (const float*)d_in[8];
    const float* mlp1_b2 = (const float*)d_in[9];
    const float* w1_W    = (const float*)d_in[10];
    const float* w1_b    = (const float*)d_in[11];
    const float* pa_r    = (const float*)d_in[12];
    const float* pa_w    = (const float*)d_in[13];
    const float* blk_W1  = (const float*)d_in[14];
    const float* blk_b1  = (const float*)d_in[15];
    const float* blk_W2  = (const float*)d_in[16];
    const float* blk_b2  = (const float*)d_in[17];
    const float* wi_W    = (const float*)d_in[18];
    const float* wi_b    = (const float*)d_in[19];
    const float* up_r    = (const float*)d_in[20];
    const float* up_w    = (const float*)d_in[21];
    const float* mlp2_W1 = (const float*)d_in[22];
    const float* mlp2_b1 = (const float*)d_in[23];
    const float* mlp2_W2 = (const float*)d_in[24];
    const float* mlp2_b2 = (const float*)d_in[25];
    const float* w2_W    = (const float*)d_in[26];
    const float* w2_b    = (const float*)d_in[27];
    const float* de_W1   = (const float*)d_in[28];
    const float* de_b1   = (const float*)d_in[29];
    const float* de_W2   = (const float*)d_in[30];
    const float* de_b2   = (const float*)d_in[31];
    float* outp = (float*)d_out;

    float*  en = symf(g_en);
    float*  x  = symf(g_x);
    float*  hb = symf(g_h);
    float*  tb = symf(g_t);
    float*  rb = symf(g_r);
    float*  vb = symf(g_v);
    float*  wc = symf(g_wcat);
    float2* rsp;
    { void* p = nullptr; cudaGetSymbolAddress(&p, g_rowstats); rsp = (float2*)p; }

    cudaFuncSetAttribute(gemm128_kernel, cudaFuncAttributeMaxDynamicSharedMemorySize, GEMM_SMEM);

    dim3 agrid(NN / 64, HH, BB);

    rowstats_kernel<<<BN / 8, 256>>>(md, rsp);
    enc_kernel<<<BN, HID>>>(inputs, en_W, en_b, en);

    // ---- stage 1 (input en, masked mhpa) ----
    repack_kernel<<<64, 256>>>(down_w, wc);
    gemm128_kernel<<<BN / 32, 256, GEMM_SMEM>>>(en, wc, nullptr, nullptr, vb, 0);
    attn_kernel<1><<<agrid, 256, ATTN_SMEM>>>(md, vb, down_r, rsp, hb);
    gemm128_kernel<<<BN / 32, 256, GEMM_SMEM>>>(en, w1_W, w1_b, nullptr, rb, 0);
    gemm128_kernel<<<BN / 32, 256, GEMM_SMEM>>>(hb, mlp1_W1, mlp1_b1, nullptr, tb, 1);
    gemm128_kernel<<<BN / 32, 256, GEMM_SMEM>>>(tb, mlp1_W2, mlp1_b2, rb, x, 1);

    // ---- 4 unmasked blocks ----
    for (int i = 0; i < 4; ++i) {
        repack_kernel<<<64, 256>>>(pa_w + (size_t)i * HH * HID * VD, wc);
        gemm128_kernel<<<BN / 32, 256, GEMM_SMEM>>>(x, wc, nullptr, nullptr, vb, 0);
        attn_kernel<0><<<agrid, 256, ATTN_SMEM>>>(md, vb, pa_r + (size_t)i * HH, rsp, hb);
        gemm128_kernel<<<BN / 32, 256, GEMM_SMEM>>>(x, wi_W + (size_t)i * HID * HID, wi_b + (size_t)i * HID, nullptr, rb, 0);
        gemm128_kernel<<<BN / 32, 256, GEMM_SMEM>>>(hb, blk_W1 + (size_t)i * HID * HID, blk_b1 + (size_t)i * HID, nullptr, tb, 1);
        gemm128_kernel<<<BN / 32, 256, GEMM_SMEM>>>(tb, blk_W2 + (size_t)i * HID * HID, blk_b2 + (size_t)i * HID, rb, x, 1);
    }

    // ---- stage 2 (masked mhpa) ----
    repack_kernel<<<64, 256>>>(up_w, wc);
    gemm128_kernel<<<BN / 32, 256, GEMM_SMEM>>>(x, wc, nullptr, nullptr, vb, 0);
    attn_kernel<1><<<agrid, 256, ATTN_SMEM>>>(md, vb, up_r, rsp, hb);
    gemm128_kernel<<<BN / 32, 256, GEMM_SMEM>>>(x, w2_W, w2_b, nullptr, rb, 0);
    gemm128_kernel<<<BN / 32, 256, GEMM_SMEM>>>(hb, mlp2_W1, mlp2_b1, nullptr, tb, 1);
    gemm128_kernel<<<BN / 32, 256, GEMM_SMEM>>>(tb, mlp2_W2, mlp2_b2, rb, x, 1);   // x = de

    // ---- decoder ----
    gemm128_kernel<<<BN / 32, 256, GEMM_SMEM>>>(x, de_W1, de_b1, nullptr, tb, 1);
    final_kernel<<<BN / 8, 256>>>(tb, de_W2, de_b2, outp);
}